// round 10
// baseline (speedup 1.0000x reference)
#include <cuda_runtime.h>
#include <cuda_fp16.h>
#include <cstdint>

// Problem constants: B=2,H=16,N=4096,D=64,F=256
#define BHp   32
#define Np    4096
#define Dp    64
#define Fp    256
#define CHUNK 64
#define GROUPS 16
#define ROWS_PER_GROUP 256
#define CHUNKS_PER_GROUP 4

// f16 tile strides (halves); int8 tile strides (bytes)
#define VT_S  72
#define KPT_S 72
#define QP_S  264
#define KVT_S 264
#define X8_S  80
#define P8_S  80

// int8 quantization constants
#define S1X   (5.75f / 127.0f)
#define INVS1 (127.0f / 5.75f)
#define S2X   (S1X / 254.0f)
#define INVS2 (254.0f * 127.0f / 5.75f)
#define T1P   (4.6f / 127.0f)
#define INVT1 (127.0f / 4.6f)
#define T2P   (T1P / 254.0f)
#define INVT2 (254.0f * 127.0f / 4.6f)
#define SCL   (S1X * T1P)
#define C1W   (1.0f / 254.0f)
#define C2W   (1.0f / (254.0f * 254.0f))

__device__ float g_kv[BHp * Fp * Dp];
__device__ float g_ksum[BHp * Fp];

__global__ void zero_scratch() {
    int i = blockIdx.x * blockDim.x + threadIdx.x;
    if (i < BHp * Fp * Dp) g_kv[i] = 0.0f;
    if (i < BHp * Fp)      g_ksum[i] = 0.0f;
}

// f16 m16n8k16 mma, f32 acc
__device__ __forceinline__ void mma16816(float* c,
                                         unsigned a0, unsigned a1, unsigned a2, unsigned a3,
                                         unsigned b0, unsigned b1) {
    asm volatile(
        "mma.sync.aligned.m16n8k16.row.col.f32.f16.f16.f32 "
        "{%0,%1,%2,%3},{%4,%5,%6,%7},{%8,%9},{%0,%1,%2,%3};"
        : "+f"(c[0]), "+f"(c[1]), "+f"(c[2]), "+f"(c[3])
        : "r"(a0), "r"(a1), "r"(a2), "r"(a3), "r"(b0), "r"(b1));
}
// s8 m16n8k32 mma, s32 acc
__device__ __forceinline__ void mma_s8(int* c,
                                       unsigned a0, unsigned a1, unsigned a2, unsigned a3,
                                       unsigned b0, unsigned b1) {
    asm volatile(
        "mma.sync.aligned.m16n8k32.row.col.s32.s8.s8.s32 "
        "{%0,%1,%2,%3},{%4,%5,%6,%7},{%8,%9},{%0,%1,%2,%3};"
        : "+r"(c[0]), "+r"(c[1]), "+r"(c[2]), "+r"(c[3])
        : "r"(a0), "r"(a1), "r"(a2), "r"(a3), "r"(b0), "r"(b1));
}

__device__ __forceinline__ unsigned lds_u32h(const __half* p) { return *(const unsigned*)p; }
__device__ __forceinline__ unsigned lds_u32b(const char* p)   { return *(const unsigned*)p; }

__device__ __forceinline__ void cpasync16(void* dst_smem, const void* src) {
    uint32_t d = (uint32_t)__cvta_generic_to_shared(dst_smem);
    asm volatile("cp.async.cg.shared.global [%0], [%1], 16;" :: "r"(d), "l"(src));
}
#define CP_COMMIT() asm volatile("cp.async.commit_group;" ::: "memory")
#define CP_WAIT0()  asm volatile("cp.async.wait_group 0;" ::: "memory")

__device__ __forceinline__ float clamp127(float v) {
    return fminf(127.0f, fmaxf(-127.0f, v));
}

// Quantize P into int8 hi/lo tiles PT8[f][d] (stride P8_S bytes)
__device__ __forceinline__ void load_P8(const float* __restrict__ P,
                                        char* PH, char* PL, int tid) {
    for (int j = tid; j < Dp * Fp / 4; j += 256) {
        float4 v = ((const float4*)P)[j];
        int d = j >> 6;
        int f0 = (j & 63) * 4;
        #pragma unroll
        for (int u = 0; u < 4; u++) {
            float x = (&v.x)[u];
            float ph = clamp127(rintf(x * INVT1));
            float pl = clamp127(rintf((x - ph * T1P) * INVT2));
            PH[(f0 + u) * P8_S + d] = (char)(int)ph;
            PL[(f0 + u) * P8_S + d] = (char)(int)pl;
        }
    }
}

// int8 projection: pr[16][4] (raw units; logits = pr*SCL)
__device__ __forceinline__ void proj_i8(const char* XH, const char* XL,
                                        const char* PH, const char* PL,
                                        int m0, int fbase, int lane,
                                        float pr[16][4]) {
    const int r  = lane >> 2;
    const int q4 = (lane & 3) * 4;
    int acc[16][4];

    // pass A: xh * ph
    #pragma unroll
    for (int t = 0; t < 16; t++) { acc[t][0]=0; acc[t][1]=0; acc[t][2]=0; acc[t][3]=0; }
    #pragma unroll
    for (int k0 = 0; k0 < 64; k0 += 32) {
        const char* ar0 = XH + (m0 + r) * X8_S + k0 + q4;
        const char* ar1 = XH + (m0 + r + 8) * X8_S + k0 + q4;
        unsigned a0 = lds_u32b(ar0), a1 = lds_u32b(ar1);
        unsigned a2 = lds_u32b(ar0 + 16), a3 = lds_u32b(ar1 + 16);
        #pragma unroll
        for (int t = 0; t < 16; t++) {
            const char* bp = PH + (fbase + t * 8 + r) * P8_S + k0 + q4;
            mma_s8(acc[t], a0, a1, a2, a3, lds_u32b(bp), lds_u32b(bp + 16));
        }
    }
    #pragma unroll
    for (int t = 0; t < 16; t++)
        #pragma unroll
        for (int u = 0; u < 4; u++) pr[t][u] = (float)acc[t][u];

    // pass B: xh * pl + xl * ph
    #pragma unroll
    for (int t = 0; t < 16; t++) { acc[t][0]=0; acc[t][1]=0; acc[t][2]=0; acc[t][3]=0; }
    #pragma unroll
    for (int k0 = 0; k0 < 64; k0 += 32) {
        const char* ah0p = XH + (m0 + r) * X8_S + k0 + q4;
        const char* ah1p = XH + (m0 + r + 8) * X8_S + k0 + q4;
        const char* al0p = XL + (m0 + r) * X8_S + k0 + q4;
        const char* al1p = XL + (m0 + r + 8) * X8_S + k0 + q4;
        unsigned ah0 = lds_u32b(ah0p), ah1 = lds_u32b(ah1p);
        unsigned ah2 = lds_u32b(ah0p + 16), ah3 = lds_u32b(ah1p + 16);
        unsigned al0 = lds_u32b(al0p), al1 = lds_u32b(al1p);
        unsigned al2 = lds_u32b(al0p + 16), al3 = lds_u32b(al1p + 16);
        #pragma unroll
        for (int t = 0; t < 16; t++) {
            const char* bhp = PH + (fbase + t * 8 + r) * P8_S + k0 + q4;
            const char* blp = PL + (fbase + t * 8 + r) * P8_S + k0 + q4;
            unsigned bh0 = lds_u32b(bhp), bh1 = lds_u32b(bhp + 16);
            unsigned bl0 = lds_u32b(blp), bl1 = lds_u32b(blp + 16);
            mma_s8(acc[t], ah0, ah1, ah2, ah3, bl0, bl1);
            mma_s8(acc[t], al0, al1, al2, al3, bh0, bh1);
        }
    }
    #pragma unroll
    for (int t = 0; t < 16; t++)
        #pragma unroll
        for (int u = 0; u < 4; u++) pr[t][u] = fmaf((float)acc[t][u], C1W, pr[t][u]);

    // pass C: xl * pl
    #pragma unroll
    for (int t = 0; t < 16; t++) { acc[t][0]=0; acc[t][1]=0; acc[t][2]=0; acc[t][3]=0; }
    #pragma unroll
    for (int k0 = 0; k0 < 64; k0 += 32) {
        const char* ar0 = XL + (m0 + r) * X8_S + k0 + q4;
        const char* ar1 = XL + (m0 + r + 8) * X8_S + k0 + q4;
        unsigned a0 = lds_u32b(ar0), a1 = lds_u32b(ar1);
        unsigned a2 = lds_u32b(ar0 + 16), a3 = lds_u32b(ar1 + 16);
        #pragma unroll
        for (int t = 0; t < 16; t++) {
            const char* bp = PL + (fbase + t * 8 + r) * P8_S + k0 + q4;
            mma_s8(acc[t], a0, a1, a2, a3, lds_u32b(bp), lds_u32b(bp + 16));
        }
    }
    #pragma unroll
    for (int t = 0; t < 16; t++)
        #pragma unroll
        for (int u = 0; u < 4; u++) pr[t][u] = fmaf((float)acc[t][u], C2W, pr[t][u]);
}

// Row-max partials -> RMAX[half][64] (raw pr units; SCL>0 so monotonic)
__device__ __forceinline__ void rowmax_store(float pr[16][4], float* RMAX,
                                             int m0, int half, int lane) {
    const int r = lane >> 2;
    float mlo = -3.4e38f, mhi = -3.4e38f;
    #pragma unroll
    for (int t = 0; t < 16; t++) {
        mlo = fmaxf(mlo, fmaxf(pr[t][0], pr[t][1]));
        mhi = fmaxf(mhi, fmaxf(pr[t][2], pr[t][3]));
    }
    #pragma unroll
    for (int off = 1; off <= 2; off <<= 1) {
        mlo = fmaxf(mlo, __shfl_xor_sync(0xffffffffu, mlo, off));
        mhi = fmaxf(mhi, __shfl_xor_sync(0xffffffffu, mhi, off));
    }
    if ((lane & 3) == 0) {
        RMAX[half * 64 + m0 + r]     = mlo;
        RMAX[half * 64 + m0 + 8 + r] = mhi;
    }
}

// quantize one float -> (hi, lo) int8
__device__ __forceinline__ void q8x(float x, char& h, char& l) {
    float xh = clamp127(rintf(x * INVS1));
    float xl = clamp127(rintf((x - xh * S1X) * INVS2));
    h = (char)(int)xh;
    l = (char)(int)xl;
}

// ---------------------------------------------------------------------------
// kside: k' projection (int8) + kv += k'^T v (f16) + ksum
// ---------------------------------------------------------------------------
__global__ __launch_bounds__(256, 1)
void kside_kernel(const float* __restrict__ K,
                  const float* __restrict__ V,
                  const float* __restrict__ P) {
    extern __shared__ char smraw[];
    char*   PH  = smraw;                          // [256][80] int8
    char*   PL  = PH + Fp * P8_S;                 // 20480
    char*   XH  = PL + Fp * P8_S;                 // [64][80]
    char*   XL  = XH + CHUNK * X8_S;
    __half* VT  = (__half*)(XL + CHUNK * X8_S);   // [64 e][72 r]
    __half* KPT = VT + CHUNK * VT_S;              // [256 f][72 r]
    float*  RMAX = (float*)(KPT + Fp * KPT_S);    // [2][64]
    float4* SK = (float4*)(RMAX + 128);           // [1024]
    float4* SV = SK + 1024;                       // [1024]

    const int tid  = threadIdx.x;
    const int w    = tid >> 5;
    const int lane = tid & 31;
    const int pair = blockIdx.y;
    const int grp  = blockIdx.x;
    const int r  = lane >> 2;
    const int q2 = (lane & 3) * 2;

    // prologue: stage chunk 0 while quantizing P
    {
        const float4* ksrc = (const float4*)(K + ((size_t)pair * Np + grp * ROWS_PER_GROUP) * Dp);
        const float4* vsrc = (const float4*)(V + ((size_t)pair * Np + grp * ROWS_PER_GROUP) * Dp);
        #pragma unroll
        for (int i = 0; i < 4; i++) {
            int j = tid + 256 * i;
            cpasync16(&SK[j], &ksrc[j]);
            cpasync16(&SV[j], &vsrc[j]);
        }
        CP_COMMIT();
    }
    load_P8(P, PH, PL, tid);

    float accv[2][8][4];
    #pragma unroll
    for (int mi = 0; mi < 2; mi++)
        #pragma unroll
        for (int t = 0; t < 8; t++)
            #pragma unroll
            for (int u = 0; u < 4; u++) accv[mi][t][u] = 0.f;
    float ksp = 0.f;

    for (int c = 0; c < CHUNKS_PER_GROUP; c++) {
        CP_WAIT0();
        __syncthreads();

        // convert stage -> XH/XL int8, VT f16
        #pragma unroll
        for (int i = 0; i < 4; i++) {
            int j = tid + 256 * i;
            float4 xv = SK[j];
            float4 vv = SV[j];
            int rr = j >> 4;
            int d0 = (j & 15) * 4;
            char h[4], l[4];
            #pragma unroll
            for (int u = 0; u < 4; u++) {
                q8x((&xv.x)[u], h[u], l[u]);
                VT[(d0 + u) * VT_S + rr] = __float2half_rn((&vv.x)[u]);
            }
            *(char4*)(XH + rr * X8_S + d0) = make_char4(h[0], h[1], h[2], h[3]);
            *(char4*)(XL + rr * X8_S + d0) = make_char4(l[0], l[1], l[2], l[3]);
        }
        __syncthreads();

        // prefetch next chunk (hidden under proj mma)
        if (c + 1 < CHUNKS_PER_GROUP) {
            const int row1 = grp * ROWS_PER_GROUP + (c + 1) * CHUNK;
            const float4* ksrc = (const float4*)(K + ((size_t)pair * Np + row1) * Dp);
            const float4* vsrc = (const float4*)(V + ((size_t)pair * Np + row1) * Dp);
            #pragma unroll
            for (int i = 0; i < 4; i++) {
                int j = tid + 256 * i;
                cpasync16(&SK[j], &ksrc[j]);
                cpasync16(&SV[j], &vsrc[j]);
            }
            CP_COMMIT();
        }

        const int m0 = (w >> 1) * 16;
        const int fbase = (w & 1) * 128;
        float pr[16][4];
        proj_i8(XH, XL, PH, PL, m0, fbase, lane, pr);
        rowmax_store(pr, RMAX, m0, (w & 1), lane);
        __syncthreads();

        // exp + transposed store into KPT[f][row]
        {
            const float Mlo = fmaxf(RMAX[m0 + r],     RMAX[64 + m0 + r]);
            const float Mhi = fmaxf(RMAX[m0 + 8 + r], RMAX[64 + m0 + 8 + r]);
            #pragma unroll
            for (int t = 0; t < 16; t++) {
                const int f = fbase + t * 8 + q2;
                KPT[f * KPT_S + m0 + r]           = __float2half_rn(__expf((pr[t][0] - Mlo) * SCL) * 0.0625f);
                KPT[(f + 1) * KPT_S + m0 + r]     = __float2half_rn(__expf((pr[t][1] - Mlo) * SCL) * 0.0625f);
                KPT[f * KPT_S + m0 + 8 + r]       = __float2half_rn(__expf((pr[t][2] - Mhi) * SCL) * 0.0625f);
                KPT[(f + 1) * KPT_S + m0 + 8 + r] = __float2half_rn(__expf((pr[t][3] - Mhi) * SCL) * 0.0625f);
            }
        }
        __syncthreads();

        // kv += k'^T v : D[f][e], A=KPT[f][r], B=VT[e][r]  (f16)
        const int fw = w * 32;
        #pragma unroll
        for (int k0 = 0; k0 < 64; k0 += 16) {
            unsigned a[2][4];
            #pragma unroll
            for (int mi = 0; mi < 2; mi++) {
                const int base0 = (fw + mi * 16 + r) * KPT_S + k0 + q2;
                const int base1 = (fw + mi * 16 + 8 + r) * KPT_S + k0 + q2;
                a[mi][0] = lds_u32h(KPT + base0);
                a[mi][1] = lds_u32h(KPT + base1);
                a[mi][2] = lds_u32h(KPT + base0 + 8);
                a[mi][3] = lds_u32h(KPT + base1 + 8);
            }
            #pragma unroll
            for (int t = 0; t < 8; t++) {
                const int vb = (t * 8 + r) * VT_S + k0 + q2;
                unsigned b0 = lds_u32h(VT + vb);
                unsigned b1 = lds_u32h(VT + vb + 8);
                mma16816(accv[0][t], a[0][0], a[0][1], a[0][2], a[0][3], b0, b1);
                mma16816(accv[1][t], a[1][0], a[1][1], a[1][2], a[1][3], b0, b1);
            }
        }

        // ksum partial
        {
            const __half2* rowp = (const __half2*)(KPT + tid * KPT_S);
            float sx = 0.f, sy = 0.f;
            #pragma unroll
            for (int j = 0; j < 32; j++) {
                float2 f2 = __half22float2(rowp[j]);
                sx += f2.x; sy += f2.y;
            }
            ksp += sx + sy;
        }
    }

    float* kvg = g_kv + (size_t)pair * Fp * Dp;
    #pragma unroll
    for (int mi = 0; mi < 2; mi++) {
        const int f0 = w * 32 + mi * 16 + r;
        #pragma unroll
        for (int t = 0; t < 8; t++) {
            const int e = t * 8 + q2;
            atomicAdd(&kvg[f0 * Dp + e],           accv[mi][t][0]);
            atomicAdd(&kvg[f0 * Dp + e + 1],       accv[mi][t][1]);
            atomicAdd(&kvg[(f0 + 8) * Dp + e],     accv[mi][t][2]);
            atomicAdd(&kvg[(f0 + 8) * Dp + e + 1], accv[mi][t][3]);
        }
    }
    atomicAdd(&g_ksum[(size_t)pair * Fp + tid], ksp);
}

// ---------------------------------------------------------------------------
// qside: q' projection (int8) + out = (q' kv) / (q' (ksum+1e-6))
// ---------------------------------------------------------------------------
__global__ __launch_bounds__(256, 1)
void qside_kernel(const float* __restrict__ Q,
                  const float* __restrict__ P,
                  float* __restrict__ out) {
    extern __shared__ char smraw[];
    char*   PH  = smraw;                           // [256][80]
    char*   PL  = PH + Fp * P8_S;
    char*   XH  = PL + Fp * P8_S;                  // [64][80]
    char*   XL  = XH + CHUNK * X8_S;
    __half* QP  = (__half*)(XL + CHUNK * X8_S);    // [64 row][264 f]
    __half* KVTh = QP + CHUNK * QP_S;              // [64 e][264 f]
    float*  KSS  = (float*)(KVTh + CHUNK * KVT_S); // [256]
    float*  RMAX = KSS + Fp;                       // [2][64]
    float*  DNI  = RMAX + 128;                     // [64]
    float4* SQ   = (float4*)(DNI + 64);            // [1024]

    const int tid  = threadIdx.x;
    const int w    = tid >> 5;
    const int lane = tid & 31;
    const int pair = blockIdx.y;
    const int grp  = blockIdx.x;
    const int r  = lane >> 2;
    const int q2 = (lane & 3) * 2;

    {
        const float4* qsrc = (const float4*)(Q + ((size_t)pair * Np + grp * ROWS_PER_GROUP) * Dp);
        #pragma unroll
        for (int i = 0; i < 4; i++) {
            int j = tid + 256 * i;
            cpasync16(&SQ[j], &qsrc[j]);
        }
        CP_COMMIT();
    }
    load_P8(P, PH, PL, tid);

    {
        const float* kvg = g_kv + (size_t)pair * Fp * Dp;
        for (int j = tid; j < Fp * Dp / 4; j += 256) {
            float4 v = ((const float4*)kvg)[j];
            int f = j / (Dp / 4);
            int e0 = (j % (Dp / 4)) * 4;
            #pragma unroll
            for (int u = 0; u < 4; u++)
                KVTh[(e0 + u) * KVT_S + f] = __float2half_rn((&v.x)[u]);
        }
        if (tid < Fp) KSS[tid] = g_ksum[(size_t)pair * Fp + tid] + 1e-6f;
    }

    for (int c = 0; c < CHUNKS_PER_GROUP; c++) {
        CP_WAIT0();
        __syncthreads();

        #pragma unroll
        for (int i = 0; i < 4; i++) {
            int j = tid + 256 * i;
            float4 xv = SQ[j];
            int rr = j >> 4;
            int d0 = (j & 15) * 4;
            char h[4], l[4];
            #pragma unroll
            for (int u = 0; u < 4; u++) q8x((&xv.x)[u], h[u], l[u]);
            *(char4*)(XH + rr * X8_S + d0) = make_char4(h[0], h[1], h[2], h[3]);
            *(char4*)(XL + rr * X8_S + d0) = make_char4(l[0], l[1], l[2], l[3]);
        }
        __syncthreads();

        if (c + 1 < CHUNKS_PER_GROUP) {
            const int row1 = grp * ROWS_PER_GROUP + (c + 1) * CHUNK;
            const float4* qsrc = (const float4*)(Q + ((size_t)pair * Np + row1) * Dp);
            #pragma unroll
            for (int i = 0; i < 4; i++) {
                int j = tid + 256 * i;
                cpasync16(&SQ[j], &qsrc[j]);
            }
            CP_COMMIT();
        }

        const int m0 = (w >> 1) * 16;
        const int fbase = (w & 1) * 128;
        float pr[16][4];
        proj_i8(XH, XL, PH, PL, m0, fbase, lane, pr);
        rowmax_store(pr, RMAX, m0, (w & 1), lane);
        __syncthreads();

        // exp + row-major store QP[row][f] (half2)
        {
            const float Mlo = fmaxf(RMAX[m0 + r],     RMAX[64 + m0 + r]);
            const float Mhi = fmaxf(RMAX[m0 + 8 + r], RMAX[64 + m0 + 8 + r]);
            #pragma unroll
            for (int t = 0; t < 16; t++) {
                const int f = fbase + t * 8 + q2;
                __half2 lo2 = __floats2half2_rn(__expf((pr[t][0] - Mlo) * SCL) * 0.0625f,
                                                __expf((pr[t][1] - Mlo) * SCL) * 0.0625f);
                __half2 hi2 = __floats2half2_rn(__expf((pr[t][2] - Mhi) * SCL) * 0.0625f,
                                                __expf((pr[t][3] - Mhi) * SCL) * 0.0625f);
                *(__half2*)(QP + (m0 + r) * QP_S + f)     = lo2;
                *(__half2*)(QP + (m0 + 8 + r) * QP_S + f) = hi2;
            }
        }
        __syncthreads();

        // denom
        {
            #pragma unroll
            for (int rr = 0; rr < 8; rr++) {
                const int row = w * 8 + rr;
                float s = 0.f;
                #pragma unroll
                for (int j = 0; j < 8; j++) {
                    const int f = lane + 32 * j;
                    s = fmaf(__half2float(QP[row * QP_S + f]), KSS[f], s);
                }
                #pragma unroll
                for (int off = 16; off > 0; off >>= 1)
                    s += __shfl_xor_sync(0xffffffffu, s, off);
                if (lane == 0) DNI[row] = 1.0f / s;
            }
        }

        // out mma: D[row][e], A=QP[row][f], B=KVTh[e][f]  (f16)
        const int om0 = (w >> 1) * 16;
        const int nb  = (w & 1) * 32;
        float oc[4][4];
        #pragma unroll
        for (int t = 0; t < 4; t++)
            #pragma unroll
            for (int u = 0; u < 4; u++) oc[t][u] = 0.f;

        #pragma unroll
        for (int k0 = 0; k0 < 256; k0 += 16) {
            const int ab0 = (om0 + r) * QP_S + k0 + q2;
            const int ab1 = (om0 + 8 + r) * QP_S + k0 + q2;
            unsigned a0 = lds_u32h(QP + ab0);
            unsigned a1 = lds_u32h(QP + ab1);
            unsigned a2 = lds_u32h(QP + ab0 + 8);
            unsigned a3 = lds_u32h(QP + ab1 + 8);
            #pragma unroll
            for (int t = 0; t < 4; t++) {
                const int bb = (nb + t * 8 + r) * KVT_S + k0 + q2;
                unsigned bh0 = lds_u32h(KVTh + bb);
                unsigned bh1 = lds_u32h(KVTh + bb + 8);
                mma16816(oc[t], a0, a1, a2, a3, bh0, bh1);
            }
        }
        __syncthreads();   // DNI visible

        float* od = out + ((size_t)pair * Np + grp * ROWS_PER_GROUP + c * CHUNK) * Dp;
        const float ilo = DNI[om0 + r];
        const float ihi = DNI[om0 + 8 + r];
        #pragma unroll
        for (int t = 0; t < 4; t++) {
            const int e = nb + t * 8 + q2;
            float2 v0 = make_float2(oc[t][0] * ilo, oc[t][1] * ilo);
            float2 v1 = make_float2(oc[t][2] * ihi, oc[t][3] * ihi);
            *(float2*)&od[(om0 + r) * Dp + e]     = v0;
            *(float2*)&od[(om0 + 8 + r) * Dp + e] = v1;
        }
    }
}

// ---------------------------------------------------------------------------
extern "C" void kernel_launch(void* const* d_in, const int* in_sizes, int n_in,
                              void* d_out, int out_size) {
    const float* q = (const float*)d_in[0];
    const float* k = (const float*)d_in[1];
    const float* v = (const float*)d_in[2];
    const float* p = (const float*)d_in[3];
    float* out = (float*)d_out;

    // kside: P8 40960 + X8 10240 + VT 9216 + KPT 36864 + RMAX 512 + stage 32768
    const size_t smemA = (size_t)(2 * Fp * P8_S + 2 * CHUNK * X8_S)
                         + (size_t)(CHUNK * VT_S + Fp * KPT_S) * 2
                         + 128 * 4 + 2 * 1024 * 16;
    // qside: P8 40960 + X8 10240 + QP 33792 + KVT 33792 + misc 1792 + stage 16384
    const size_t smemB = (size_t)(2 * Fp * P8_S + 2 * CHUNK * X8_S)
                         + (size_t)(CHUNK * QP_S + CHUNK * KVT_S) * 2
                         + (Fp + 128 + 64) * 4 + 1024 * 16;

    cudaFuncSetAttribute(kside_kernel, cudaFuncAttributeMaxDynamicSharedMemorySize, (int)smemA);
    cudaFuncSetAttribute(qside_kernel, cudaFuncAttributeMaxDynamicSharedMemorySize, (int)smemB);

    {
        int total = BHp * Fp * Dp;
        zero_scratch<<<(total + 255) / 256, 256>>>();
    }
    dim3 grid(GROUPS, BHp);
    kside_kernel<<<grid, 256, smemA>>>(k, v, p);
    qside_kernel<<<grid, 256, smemB>>>(q, p, out);
}

// round 11
// speedup vs baseline: 2.4264x; 2.4264x over previous
#include <cuda_runtime.h>
#include <cuda_fp16.h>
#include <cstdint>

// Problem constants: B=2,H=16,N=4096,D=64,F=256
#define BHp   32
#define Np    4096
#define Dp    64
#define Fp    256
#define CHUNK 64
#define GROUPS 16
#define ROWS_PER_GROUP 256
#define CHUNKS_PER_GROUP 4
#define NJOBS (BHp * GROUPS)     // 512 per phase
#define NCTA  148

// smem strides (in halves)
#define XS_S  72
#define PT_S  72
#define VT_S  72
#define KPT_S 72
#define QP_S  264
#define KVT_S 264

// smem byte offsets
#define OFF_PTH   0u
#define OFF_PTL   36864u
#define U0        73728u
#define OFF_SK    (U0)             // kside K stage (16384 B)
#define OFF_SV    (U0 + 16384u)    // kside V stage
#define OFF_SQ    (U0)             // qside Q stage (aliases SK)
#define OFF_XSH   (U0 + 32768u)
#define OFF_XSL   (U0 + 41984u)
#define OFF_VT    (U0 + 51200u)    // kside
#define OFF_KPT   (U0 + 60416u)    // kside
#define OFF_RMK   (U0 + 97280u)    // kside RMAX
#define OFF_QP    (U0 + 51200u)    // qside (aliases VT/KPT)
#define OFF_KVT   (U0 + 84992u)
#define OFF_KSS   (U0 + 118784u)
#define OFF_RMQ   (U0 + 119808u)
#define OFF_DNI   (U0 + 120320u)
#define SMEM_TOTAL (U0 + 120576u)  // 194304 B

__device__ float g_kv[BHp * Fp * Dp];
__device__ float g_ksum[BHp * Fp];
__device__ unsigned g_sync[BHp];
__device__ unsigned g_jobk;
__device__ unsigned g_jobq;

__global__ void zero_scratch() {
    int i = blockIdx.x * blockDim.x + threadIdx.x;
    if (i < BHp * Fp * Dp) g_kv[i] = 0.0f;
    if (i < BHp * Fp)      g_ksum[i] = 0.0f;
    if (i < BHp)           g_sync[i] = 0u;
    if (i == 0) { g_jobk = 0u; g_jobq = 0u; }
}

__device__ __forceinline__ void mma16816(float* c,
                                         unsigned a0, unsigned a1, unsigned a2, unsigned a3,
                                         unsigned b0, unsigned b1) {
    asm volatile(
        "mma.sync.aligned.m16n8k16.row.col.f32.f16.f16.f32 "
        "{%0,%1,%2,%3},{%4,%5,%6,%7},{%8,%9},{%0,%1,%2,%3};"
        : "+f"(c[0]), "+f"(c[1]), "+f"(c[2]), "+f"(c[3])
        : "r"(a0), "r"(a1), "r"(a2), "r"(a3), "r"(b0), "r"(b1));
}
__device__ __forceinline__ unsigned lds_u32(const __half* p) { return *(const unsigned*)p; }

__device__ __forceinline__ void cpasync16(void* dst_smem, const void* src) {
    uint32_t d = (uint32_t)__cvta_generic_to_shared(dst_smem);
    asm volatile("cp.async.cg.shared.global [%0], [%1], 16;" :: "r"(d), "l"(src));
}
#define CP_COMMIT() asm volatile("cp.async.commit_group;" ::: "memory")
#define CP_WAIT0()  asm volatile("cp.async.wait_group 0;" ::: "memory")

__device__ __forceinline__ void load_PT(const float* __restrict__ P,
                                        __half* PTh, __half* PTl, int tid) {
    for (int j = tid; j < Dp * Fp / 4; j += 256) {
        float4 v = ((const float4*)P)[j];
        int d = j >> 6;
        int f0 = (j & 63) * 4;
        #pragma unroll
        for (int u = 0; u < 4; u++) {
            float x = (&v.x)[u];
            __half hi = __float2half_rn(x);
            __half lo = __float2half_rn(x - __half2float(hi));
            PTh[(f0 + u) * PT_S + d] = hi;
            PTl[(f0 + u) * PT_S + d] = lo;
        }
    }
}

// 3-term hi/lo split projection: xh*Ph + xh*Pl + xl*Ph
__device__ __forceinline__ void proj_mma(const __half* XSh, const __half* XSl,
                                         const __half* PTh, const __half* PTl,
                                         int m0, int fbase, int lane,
                                         float pr[16][4]) {
    #pragma unroll
    for (int t = 0; t < 16; t++) {
        pr[t][0] = 0.f; pr[t][1] = 0.f; pr[t][2] = 0.f; pr[t][3] = 0.f;
    }
    const int r  = lane >> 2;
    const int q2 = (lane & 3) * 2;
    #pragma unroll
    for (int k0 = 0; k0 < 64; k0 += 16) {
        const int ar0 = (m0 + r) * XS_S + k0 + q2;
        const int ar1 = (m0 + r + 8) * XS_S + k0 + q2;
        unsigned ah0 = lds_u32(XSh + ar0);
        unsigned ah1 = lds_u32(XSh + ar1);
        unsigned ah2 = lds_u32(XSh + ar0 + 8);
        unsigned ah3 = lds_u32(XSh + ar1 + 8);
        unsigned al0 = lds_u32(XSl + ar0);
        unsigned al1 = lds_u32(XSl + ar1);
        unsigned al2 = lds_u32(XSl + ar0 + 8);
        unsigned al3 = lds_u32(XSl + ar1 + 8);
        #pragma unroll
        for (int t = 0; t < 16; t++) {
            const int fb = (fbase + t * 8 + r) * PT_S + k0 + q2;
            unsigned bh0 = lds_u32(PTh + fb);
            unsigned bh1 = lds_u32(PTh + fb + 8);
            unsigned bl0 = lds_u32(PTl + fb);
            unsigned bl1 = lds_u32(PTl + fb + 8);
            mma16816(pr[t], ah0, ah1, ah2, ah3, bh0, bh1);
            mma16816(pr[t], ah0, ah1, ah2, ah3, bl0, bl1);
            mma16816(pr[t], al0, al1, al2, al3, bh0, bh1);
        }
    }
}

__device__ __forceinline__ void rowmax_store(float pr[16][4], float* RMAX,
                                             int m0, int half, int lane) {
    const int r = lane >> 2;
    float mlo = -3.4e38f, mhi = -3.4e38f;
    #pragma unroll
    for (int t = 0; t < 16; t++) {
        mlo = fmaxf(mlo, fmaxf(pr[t][0], pr[t][1]));
        mhi = fmaxf(mhi, fmaxf(pr[t][2], pr[t][3]));
    }
    #pragma unroll
    for (int off = 1; off <= 2; off <<= 1) {
        mlo = fmaxf(mlo, __shfl_xor_sync(0xffffffffu, mlo, off));
        mhi = fmaxf(mhi, __shfl_xor_sync(0xffffffffu, mhi, off));
    }
    if ((lane & 3) == 0) {
        RMAX[half * 64 + m0 + r]     = mlo;
        RMAX[half * 64 + m0 + 8 + r] = mhi;
    }
}

// ---------------------------------------------------------------------------
// kside job: one (pair, grp) tile of 256 rows
// ---------------------------------------------------------------------------
__device__ void kside_job(const float* __restrict__ K, const float* __restrict__ V,
                          int pair, int grp, char* sm,
                          int tid, int w, int lane) {
    __half* PTh = (__half*)(sm + OFF_PTH);
    __half* PTl = (__half*)(sm + OFF_PTL);
    __half* XSh = (__half*)(sm + OFF_XSH);
    __half* XSl = (__half*)(sm + OFF_XSL);
    __half* VT  = (__half*)(sm + OFF_VT);
    __half* KPT = (__half*)(sm + OFF_KPT);
    float*  RMAX = (float*)(sm + OFF_RMK);
    float4* SK = (float4*)(sm + OFF_SK);
    float4* SV = (float4*)(sm + OFF_SV);

    const int r  = lane >> 2;
    const int q2 = (lane & 3) * 2;

    // stage chunk 0
    {
        const float4* ksrc = (const float4*)(K + ((size_t)pair * Np + grp * ROWS_PER_GROUP) * Dp);
        const float4* vsrc = (const float4*)(V + ((size_t)pair * Np + grp * ROWS_PER_GROUP) * Dp);
        #pragma unroll
        for (int i = 0; i < 4; i++) {
            int j = tid + 256 * i;
            cpasync16(&SK[j], &ksrc[j]);
            cpasync16(&SV[j], &vsrc[j]);
        }
        CP_COMMIT();
    }

    float accv[2][8][4];
    #pragma unroll
    for (int mi = 0; mi < 2; mi++)
        #pragma unroll
        for (int t = 0; t < 8; t++)
            #pragma unroll
            for (int u = 0; u < 4; u++) accv[mi][t][u] = 0.f;
    float ksp = 0.f;

    for (int c = 0; c < CHUNKS_PER_GROUP; c++) {
        CP_WAIT0();
        __syncthreads();

        #pragma unroll
        for (int i = 0; i < 4; i++) {
            int j = tid + 256 * i;
            float4 xv = SK[j];
            float4 vv = SV[j];
            int rr = j >> 4;
            int d0 = (j & 15) * 4;
            #pragma unroll
            for (int u = 0; u < 4; u++) {
                float x = (&xv.x)[u];
                __half hi = __float2half_rn(x);
                __half lo = __float2half_rn(x - __half2float(hi));
                XSh[rr * XS_S + d0 + u] = hi;
                XSl[rr * XS_S + d0 + u] = lo;
                VT[(d0 + u) * VT_S + rr] = __float2half_rn((&vv.x)[u]);
            }
        }
        __syncthreads();

        if (c + 1 < CHUNKS_PER_GROUP) {
            const int row1 = grp * ROWS_PER_GROUP + (c + 1) * CHUNK;
            const float4* ksrc = (const float4*)(K + ((size_t)pair * Np + row1) * Dp);
            const float4* vsrc = (const float4*)(V + ((size_t)pair * Np + row1) * Dp);
            #pragma unroll
            for (int i = 0; i < 4; i++) {
                int j = tid + 256 * i;
                cpasync16(&SK[j], &ksrc[j]);
                cpasync16(&SV[j], &vsrc[j]);
            }
            CP_COMMIT();
        }

        const int m0 = (w >> 1) * 16;
        const int fbase = (w & 1) * 128;
        float pr[16][4];
        proj_mma(XSh, XSl, PTh, PTl, m0, fbase, lane, pr);
        rowmax_store(pr, RMAX, m0, (w & 1), lane);
        __syncthreads();

        {
            const float Mlo = fmaxf(RMAX[m0 + r],     RMAX[64 + m0 + r]);
            const float Mhi = fmaxf(RMAX[m0 + 8 + r], RMAX[64 + m0 + 8 + r]);
            #pragma unroll
            for (int t = 0; t < 16; t++) {
                const int f = fbase + t * 8 + q2;
                KPT[f * KPT_S + m0 + r]           = __float2half_rn(__expf(pr[t][0] - Mlo) * 0.0625f);
                KPT[(f + 1) * KPT_S + m0 + r]     = __float2half_rn(__expf(pr[t][1] - Mlo) * 0.0625f);
                KPT[f * KPT_S + m0 + 8 + r]       = __float2half_rn(__expf(pr[t][2] - Mhi) * 0.0625f);
                KPT[(f + 1) * KPT_S + m0 + 8 + r] = __float2half_rn(__expf(pr[t][3] - Mhi) * 0.0625f);
            }
        }
        __syncthreads();

        const int fw = w * 32;
        #pragma unroll
        for (int k0 = 0; k0 < 64; k0 += 16) {
            unsigned a[2][4];
            #pragma unroll
            for (int mi = 0; mi < 2; mi++) {
                const int base0 = (fw + mi * 16 + r) * KPT_S + k0 + q2;
                const int base1 = (fw + mi * 16 + 8 + r) * KPT_S + k0 + q2;
                a[mi][0] = lds_u32(KPT + base0);
                a[mi][1] = lds_u32(KPT + base1);
                a[mi][2] = lds_u32(KPT + base0 + 8);
                a[mi][3] = lds_u32(KPT + base1 + 8);
            }
            #pragma unroll
            for (int t = 0; t < 8; t++) {
                const int vb = (t * 8 + r) * VT_S + k0 + q2;
                unsigned b0 = lds_u32(VT + vb);
                unsigned b1 = lds_u32(VT + vb + 8);
                mma16816(accv[0][t], a[0][0], a[0][1], a[0][2], a[0][3], b0, b1);
                mma16816(accv[1][t], a[1][0], a[1][1], a[1][2], a[1][3], b0, b1);
            }
        }

        {
            const __half2* rowp = (const __half2*)(KPT + tid * KPT_S);
            float sx = 0.f, sy = 0.f;
            #pragma unroll
            for (int j = 0; j < 32; j++) {
                float2 f2 = __half22float2(rowp[j]);
                sx += f2.x; sy += f2.y;
            }
            ksp += sx + sy;
        }
    }

    float* kvg = g_kv + (size_t)pair * Fp * Dp;
    #pragma unroll
    for (int mi = 0; mi < 2; mi++) {
        const int f0 = w * 32 + mi * 16 + r;
        #pragma unroll
        for (int t = 0; t < 8; t++) {
            const int e = t * 8 + q2;
            atomicAdd(&kvg[f0 * Dp + e],           accv[mi][t][0]);
            atomicAdd(&kvg[f0 * Dp + e + 1],       accv[mi][t][1]);
            atomicAdd(&kvg[(f0 + 8) * Dp + e],     accv[mi][t][2]);
            atomicAdd(&kvg[(f0 + 8) * Dp + e + 1], accv[mi][t][3]);
        }
    }
    atomicAdd(&g_ksum[(size_t)pair * Fp + tid], ksp);

    // release: all this CTA's contributions visible before count increment
    __syncthreads();
    __threadfence();
    if (tid == 0) atomicAdd(&g_sync[pair], 1u);
}

// ---------------------------------------------------------------------------
// qside job
// ---------------------------------------------------------------------------
__device__ void qside_job(const float* __restrict__ Q, float* __restrict__ out,
                          int pair, int grp, bool reload_kv, char* sm,
                          int tid, int w, int lane) {
    __half* PTh = (__half*)(sm + OFF_PTH);
    __half* PTl = (__half*)(sm + OFF_PTL);
    __half* XSh = (__half*)(sm + OFF_XSH);
    __half* XSl = (__half*)(sm + OFF_XSL);
    __half* QP  = (__half*)(sm + OFF_QP);
    __half* KVTh = (__half*)(sm + OFF_KVT);
    float*  KSS  = (float*)(sm + OFF_KSS);
    float*  RMAX = (float*)(sm + OFF_RMQ);
    float*  DNI  = (float*)(sm + OFF_DNI);
    float4* SQ   = (float4*)(sm + OFF_SQ);

    const int r  = lane >> 2;
    const int q2 = (lane & 3) * 2;

    // stage chunk 0
    {
        const float4* qsrc = (const float4*)(Q + ((size_t)pair * Np + grp * ROWS_PER_GROUP) * Dp);
        #pragma unroll
        for (int i = 0; i < 4; i++) {
            int j = tid + 256 * i;
            cpasync16(&SQ[j], &qsrc[j]);
        }
        CP_COMMIT();
    }

    if (reload_kv) {
        const float4* kvg = (const float4*)(g_kv + (size_t)pair * Fp * Dp);
        for (int j = tid; j < Fp * Dp / 4; j += 256) {
            float4 v = __ldcg(&kvg[j]);
            int f = j >> 4;
            int e0 = (j & 15) * 4;
            #pragma unroll
            for (int u = 0; u < 4; u++)
                KVTh[(e0 + u) * KVT_S + f] = __float2half_rn((&v.x)[u]);
        }
        KSS[tid] = __ldcg(&g_ksum[(size_t)pair * Fp + tid]) + 1e-6f;
    }

    for (int c = 0; c < CHUNKS_PER_GROUP; c++) {
        CP_WAIT0();
        __syncthreads();

        #pragma unroll
        for (int i = 0; i < 4; i++) {
            int j = tid + 256 * i;
            float4 xv = SQ[j];
            int rr = j >> 4;
            int d0 = (j & 15) * 4;
            #pragma unroll
            for (int u = 0; u < 4; u++) {
                float x = (&xv.x)[u];
                __half hi = __float2half_rn(x);
                __half lo = __float2half_rn(x - __half2float(hi));
                XSh[rr * XS_S + d0 + u] = hi;
                XSl[rr * XS_S + d0 + u] = lo;
            }
        }
        __syncthreads();

        if (c + 1 < CHUNKS_PER_GROUP) {
            const int row1 = grp * ROWS_PER_GROUP + (c + 1) * CHUNK;
            const float4* qsrc = (const float4*)(Q + ((size_t)pair * Np + row1) * Dp);
            #pragma unroll
            for (int i = 0; i < 4; i++) {
                int j = tid + 256 * i;
                cpasync16(&SQ[j], &qsrc[j]);
            }
            CP_COMMIT();
        }

        const int m0 = (w >> 1) * 16;
        const int fbase = (w & 1) * 128;
        float pr[16][4];
        proj_mma(XSh, XSl, PTh, PTl, m0, fbase, lane, pr);
        rowmax_store(pr, RMAX, m0, (w & 1), lane);
        __syncthreads();

        {
            const float Mlo = fmaxf(RMAX[m0 + r],     RMAX[64 + m0 + r]);
            const float Mhi = fmaxf(RMAX[m0 + 8 + r], RMAX[64 + m0 + 8 + r]);
            #pragma unroll
            for (int t = 0; t < 16; t++) {
                const int f = fbase + t * 8 + q2;
                __half2 lo2 = __floats2half2_rn(__expf(pr[t][0] - Mlo) * 0.0625f,
                                                __expf(pr[t][1] - Mlo) * 0.0625f);
                __half2 hi2 = __floats2half2_rn(__expf(pr[t][2] - Mhi) * 0.0625f,
                                                __expf(pr[t][3] - Mhi) * 0.0625f);
                *(__half2*)(QP + (m0 + r) * QP_S + f)     = lo2;
                *(__half2*)(QP + (m0 + 8 + r) * QP_S + f) = hi2;
            }
        }
        __syncthreads();

        {
            #pragma unroll
            for (int rr = 0; rr < 8; rr++) {
                const int row = w * 8 + rr;
                float s = 0.f;
                #pragma unroll
                for (int j = 0; j < 8; j++) {
                    const int f = lane + 32 * j;
                    s = fmaf(__half2float(QP[row * QP_S + f]), KSS[f], s);
                }
                #pragma unroll
                for (int off = 16; off > 0; off >>= 1)
                    s += __shfl_xor_sync(0xffffffffu, s, off);
                if (lane == 0) DNI[row] = 1.0f / s;
            }
        }

        const int om0 = (w >> 1) * 16;
        const int nb  = (w & 1) * 32;
        float oc[4][4];
        #pragma unroll
        for (int t = 0; t < 4; t++)
            #pragma unroll
            for (int u = 0; u < 4; u++) oc[t][u] = 0.f;

        #pragma unroll
        for (int k0 = 0; k0 < 256; k0 += 16) {
            const int ab0 = (om0 + r) * QP_S + k0 + q2;
            const int ab1 = (om0 + 8 + r) * QP_S + k0 + q2;
            unsigned a0 = lds_u32(QP + ab0);
            unsigned a1 = lds_u32(QP + ab1);
            unsigned a2 = lds_u32(QP + ab0 + 8);
            unsigned a3 = lds_u32(QP + ab1 + 8);
            #pragma unroll
            for (int t = 0; t < 4; t++) {
                const int bb = (nb + t * 8 + r) * KVT_S + k0 + q2;
                unsigned bh0 = lds_u32(KVTh + bb);
                unsigned bh1 = lds_u32(KVTh + bb + 8);
                mma16816(oc[t], a0, a1, a2, a3, bh0, bh1);
            }
        }
        __syncthreads();   // DNI visible

        float* od = out + ((size_t)pair * Np + grp * ROWS_PER_GROUP + c * CHUNK) * Dp;
        const float ilo = DNI[om0 + r];
        const float ihi = DNI[om0 + 8 + r];
        #pragma unroll
        for (int t = 0; t < 4; t++) {
            const int e = nb + t * 8 + q2;
            float2 v0 = make_float2(oc[t][0] * ilo, oc[t][1] * ilo);
            float2 v1 = make_float2(oc[t][2] * ihi, oc[t][3] * ihi);
            *(float2*)&od[(om0 + r) * Dp + e]     = v0;
            *(float2*)&od[(om0 + 8 + r) * Dp + e] = v1;
        }
    }
}

// ---------------------------------------------------------------------------
// Persistent fused kernel
// ---------------------------------------------------------------------------
__global__ __launch_bounds__(256, 1)
void fused_kernel(const float* __restrict__ Q, const float* __restrict__ K,
                  const float* __restrict__ V, const float* __restrict__ P,
                  float* __restrict__ out) {
    extern __shared__ char sm[];
    __shared__ int jobS;

    const int tid  = threadIdx.x;
    const int w    = tid >> 5;
    const int lane = tid & 31;

    load_PT(P, (__half*)(sm + OFF_PTH), (__half*)(sm + OFF_PTL), tid);
    __syncthreads();

    // ---- phase 1: kside jobs ----
    for (;;) {
        if (tid == 0) jobS = (int)atomicAdd(&g_jobk, 1u);
        __syncthreads();
        const int j = jobS;
        if (j >= NJOBS) break;
        kside_job(K, V, j / GROUPS, j % GROUPS, sm, tid, w, lane);
        __syncthreads();
    }

    // ---- phase 2: qside jobs ----
    int prev_pair = -1;
    for (;;) {
        if (tid == 0) jobS = (int)atomicAdd(&g_jobq, 1u);
        __syncthreads();
        const int j = jobS;
        if (j >= NJOBS) break;
        const int pair = j / GROUPS;
        const int grp  = j % GROUPS;
        const bool reload = (pair != prev_pair);
        if (reload) {
            if (tid == 0) {
                while (atomicAdd(&g_sync[pair], 0u) < (unsigned)GROUPS) __nanosleep(100);
            }
            __syncthreads();
            __threadfence();   // acquire: order kv reads after flag observation
            prev_pair = pair;
        }
        qside_job(Q, out, pair, grp, reload, sm, tid, w, lane);
        __syncthreads();
    }
}

// ---------------------------------------------------------------------------
extern "C" void kernel_launch(void* const* d_in, const int* in_sizes, int n_in,
                              void* d_out, int out_size) {
    const float* q = (const float*)d_in[0];
    const float* k = (const float*)d_in[1];
    const float* v = (const float*)d_in[2];
    const float* p = (const float*)d_in[3];
    float* out = (float*)d_out;

    cudaFuncSetAttribute(fused_kernel, cudaFuncAttributeMaxDynamicSharedMemorySize, (int)SMEM_TOTAL);

    {
        int total = BHp * Fp * Dp;
        zero_scratch<<<(total + 255) / 256, 256>>>();
    }
    fused_kernel<<<NCTA, 256, SMEM_TOTAL>>>(q, k, v, p, out);
}